// round 16
// baseline (speedup 1.0000x reference)
#include <cuda_runtime.h>
#include <cuda_fp16.h>
#include <cstdint>
#include <math.h>

#define HDIM 1024
#define GDIM 4096
#define TT 28
#define DD 28
#define BB 4096
#define KBATCH 8

// GEMM: C[4096 x 4096gates], SINGLE fp16 term, per-K-chunk
// CTA tile 128m x 128n, warp tile 64x32, NSTAGE=3 x 32KB -> 96KB -> 2 CTA/SM
// Data pass: persistent kernel, ticket scheduler, PER-CHUNK fine deps
// Key pass : persistent kernel, ONE grid barrier/step, private h/c slices
#define KC 64
#define CPT 17            // K-chunks (16 h-chunks + 1 x-chunk)
#define NSTAGE 3
#define TILE_BYTES 16384  // 128 x 64 fp16
#define STAGE_BYTES 32768 // Ah + Bh
#define SMEM_DATA (NSTAGE * STAGE_BYTES)   // 96 KB
#define MBK 32            // 4096/128 M-blocks
#define NBK 32            // 1024/32 out-blocks (128 gate-cols per CTA)
#define NTASK (TT * MBK * NBK)
#define PGRID 296         // 2 CTAs x 148 SMs, all resident
#define KGRID 272         // key pass: 16 col-blocks x 17 chunks, all resident

// ---------------- persistent scratch ----------------
__device__ __half g_Wh[NBK][CPT][8192];
__device__ __half g_Wl[NBK][CPT][8192];
__device__ __half g_Ah[2][MBK][16][8192];   // h tiles (fp16 rounded), ping-pong
__device__ __half g_xh[TT][MBK][8192];
__device__ float g_c[(size_t)BB * HDIM];
__device__ float g_hf[(size_t)BB * HDIM];
__device__ float g_hk[2][KBATCH * HDIM];
__device__ float g_ck[KBATCH * HDIM];
__device__ float g_gk3[TT][KBATCH][GDIM];   // per-step gate buffers (no clearing)
__device__ float g_h0[HDIM];
__device__ float g_c0[HDIM];
__device__ unsigned int g_ticket;
__device__ unsigned int g_dep[TT][MBK];        // coarse: 32 tiles per (t,mb)
__device__ unsigned int g_dep2[TT][MBK][16];   // fine: per h-chunk, target 2
__device__ unsigned int g_kbar;

// ---------------- helpers ----------------
__device__ __forceinline__ float sigmoidf_(float x) { return 1.0f / (1.0f + __expf(-x)); }

// swizzled byte offset within a [rows x 64] fp16 tile (128B rows, 16B groups)
__device__ __forceinline__ uint32_t aoff(int row, int kk) {
    return (uint32_t)(row * 128 + ((((kk >> 3) ^ row) & 7) << 4) + (kk & 7) * 2);
}

__device__ __forceinline__ uint32_t smem_u32(const void* p) {
    uint32_t a;
    asm("{ .reg .u64 t; cvta.to.shared.u64 t, %1; cvt.u32.u64 %0, t; }" : "=r"(a) : "l"(p));
    return a;
}

__device__ __forceinline__ uint32_t hpack(float v0, float v1) {
    __half2 p = __floats2half2_rn(v0, v1);
    return *(uint32_t*)&p;
}

__device__ __forceinline__ unsigned int acq_load(const unsigned int* p) {
    unsigned int v;
    asm volatile("ld.acquire.gpu.global.u32 %0, [%1];" : "=r"(v) : "l"(p));
    return v;
}

__device__ __forceinline__ void dep_wait2(const unsigned int* dp) {
    for (;;) {
        if (acq_load(dp) >= 2u) break;
        __nanosleep(64);
    }
}

#define CP_ASYNC16(dst, src) \
    asm volatile("cp.async.cg.shared.global [%0], [%1], 16;" :: "r"(dst), "l"(src))
#define CP_COMMIT() asm volatile("cp.async.commit_group;" ::: "memory")
#define CP_WAIT2() asm volatile("cp.async.wait_group 2;" ::: "memory")

#define LDMX4(r0, r1, r2, r3, addr) \
    asm volatile("ldmatrix.sync.aligned.m8n8.x4.shared.b16 {%0,%1,%2,%3}, [%4];" \
        : "=r"(r0), "=r"(r1), "=r"(r2), "=r"(r3) : "r"(addr))
#define MMA16816(d, a, b0, b1) \
    asm volatile("mma.sync.aligned.m16n8k16.row.col.f32.f16.f16.f32 " \
        "{%0,%1,%2,%3},{%4,%5,%6,%7},{%8,%9},{%0,%1,%2,%3};" \
        : "+f"((d)[0]), "+f"((d)[1]), "+f"((d)[2]), "+f"((d)[3]) \
        : "r"((a)[0]), "r"((a)[1]), "r"((a)[2]), "r"((a)[3]), "r"(b0), "r"(b1))

// ---------------------------------------------------------------------------
// prep: fp16 hi/lo split of weights into swizzled [n][k] tiles.
// B tile row layout (128): warp w (n>>5), gate ((n>>3)&3), out_local (n&7)
// -> W column = gate*1024 + nb*32 + w*8 + ol ; tile row n = w*32+gate*8+ol
// ---------------------------------------------------------------------------
__global__ void prep_W(const float* __restrict__ Wih, const float* __restrict__ Whh)
{
    int kc = blockIdx.x, nb = blockIdx.y;
    int n = threadIdx.x & 127, kh = threadIdx.x >> 7;
    int w = n >> 5, gate = (n >> 3) & 3, ol = n & 7;
    int col = gate * HDIM + nb * 32 + w * 8 + ol;
    char* th = (char*)&g_Wh[nb][kc][0];
    char* tl = (char*)&g_Wl[nb][kc][0];
#pragma unroll
    for (int kk = kh * 32; kk < kh * 32 + 32; kk += 2) {
        float v0, v1;
        if (kc < 16) {
            size_t kg = (size_t)(kc * 64 + kk);
            v0 = Whh[kg * GDIM + col];
            v1 = Whh[(kg + 1) * GDIM + col];
        } else {
            v0 = (kk < DD) ? Wih[(size_t)kk * GDIM + col] : 0.f;
            v1 = (kk + 1 < DD) ? Wih[(size_t)(kk + 1) * GDIM + col] : 0.f;
        }
        float h0 = __half2float(__float2half_rn(v0));
        float h1 = __half2float(__float2half_rn(v1));
        uint32_t off = aoff(n, kk);
        *(uint32_t*)(th + off) = hpack(h0, h1);
        *(uint32_t*)(tl + off) = hpack(v0 - h0, v1 - h1);
    }
}

__global__ void prep_x(const float* __restrict__ x)
{
    int mb = blockIdx.x, t = blockIdx.y;
    int r = threadIdx.x;
    int m = mb * 128 + r;
    char* th = (char*)&g_xh[t][mb][0];
#pragma unroll
    for (int kk = 0; kk < KC; kk += 2) {
        float v0 = (kk < DD) ? x[((size_t)m * TT + t) * DD + kk] : 0.f;
        float v1 = (kk + 1 < DD) ? x[((size_t)m * TT + t) * DD + kk + 1] : 0.f;
        *(uint32_t*)(th + aoff(r, kk)) = hpack(v0, v1);
    }
}

// ---------------------------------------------------------------------------
// Persistent data pass: ticket scheduler + fine per-chunk deps + fused cell
// Stage layout: [Ah 16K][Bh 16K]
// ---------------------------------------------------------------------------
__device__ __forceinline__ void load_chunk(uint32_t smb, int tid, int c,
                                           int t, int pp, int mb, int nb)
{
    if (c < CPT) {
        const char* ah = (c == 16) ? (const char*)&g_xh[t][mb][0]
                                   : (const char*)&g_Ah[pp][mb][c][0];
        const char* bh = (const char*)&g_Wh[nb][c][0];
        uint32_t dst = smb + (c % NSTAGE) * STAGE_BYTES;
        int o = tid * 16;
#pragma unroll
        for (int i = 0; i < 4; i++) {
            CP_ASYNC16(dst + o,              ah + o);
            CP_ASYNC16(dst + TILE_BYTES + o, bh + o);
            o += 4096;
        }
    }
    CP_COMMIT();
}

__global__ void __launch_bounds__(256, 2)
data_persist(const float* __restrict__ bias)
{
    extern __shared__ __align__(128) char sm[];
    const uint32_t smb = smem_u32(sm);
    __shared__ unsigned int s_task;
    __shared__ unsigned int s_ready;
    const int tid = threadIdx.x, wid = tid >> 5, lane = tid & 31;
    const int mw = (wid >> 2) * 64;       // warp m offset
    const int nw = (wid & 3) * 32;        // warp n(col) offset

    // lane geometry (task-invariant)
    const int a_row0 = mw + ((lane >> 3) & 1) * 8 + (lane & 7);   // + mi*16
    const int a_ghalf = lane >> 4;
    const int b_row0 = nw + ((lane >> 4) & 1) * 8 + (lane & 7);   // + 16 for ni 2,3
    const int b_ghalf = (lane >> 3) & 1;
    const int r4 = lane >> 2;

    for (;;) {
        if (tid == 0) s_task = atomicAdd(&g_ticket, 1u);
        __syncthreads();
        const unsigned int task = s_task;
        if (task >= NTASK) return;
        const int t  = task >> 10;
        const int mb = (task >> 5) & 31;
        const int nb = task & 31;
        const int pp = t & 1;

        // dep check: coarse fast-path, else fine for the 3 prefetched chunks
        if (tid == 0) {
            unsigned int r = 1u;
            if (t > 0) {
                if (acq_load(&g_dep[t - 1][mb]) < NBK) {
                    r = 0u;
                    dep_wait2(&g_dep2[t - 1][mb][0]);
                    dep_wait2(&g_dep2[t - 1][mb][1]);
                    dep_wait2(&g_dep2[t - 1][mb][2]);
                }
            }
            s_ready = r;
        }
        __syncthreads();

        float acc[4][4][4];
#pragma unroll
        for (int i = 0; i < 4; i++)
#pragma unroll
            for (int j = 0; j < 4; j++)
#pragma unroll
                for (int q = 0; q < 4; q++) acc[i][j][q] = 0.f;

        load_chunk(smb, tid, 0, t, pp, mb, nb);
        load_chunk(smb, tid, 1, t, pp, mb, nb);
        load_chunk(smb, tid, 2, t, pp, mb, nb);

        for (int c = 0; c < CPT; c++) {
            CP_WAIT2();
            __syncthreads();

            uint32_t sAh = smb + (c % NSTAGE) * STAGE_BYTES;
            uint32_t sBh = sAh + TILE_BYTES;
#pragma unroll
            for (int kb = 0; kb < 4; kb++) {
                const uint32_t acsw = (uint32_t)((((2 * kb + a_ghalf) ^ a_row0) & 7) << 4);
                const uint32_t bcsw = (uint32_t)((((2 * kb + b_ghalf) ^ b_row0) & 7) << 4);
                const uint32_t brow = (uint32_t)b_row0 * 128 + bcsw;

                uint32_t ah[4][4], bh[8];
#pragma unroll
                for (int mi = 0; mi < 4; mi++) {
                    uint32_t ad = sAh + (uint32_t)(a_row0 + mi * 16) * 128 + acsw;
                    LDMX4(ah[mi][0], ah[mi][1], ah[mi][2], ah[mi][3], ad);
                }
                LDMX4(bh[0], bh[1], bh[2], bh[3], sBh + brow);
                LDMX4(bh[4], bh[5], bh[6], bh[7], sBh + brow + 2048);
#pragma unroll
                for (int ni = 0; ni < 4; ni++)
#pragma unroll
                    for (int mi = 0; mi < 4; mi++)
                        MMA16816(acc[mi][ni], ah[mi], bh[ni * 2], bh[ni * 2 + 1]);
            }
            // fine dep for the chunk we are about to prefetch
            if (tid == 0) {
                int nc = c + NSTAGE;
                if (nc < 16 && !s_ready) {
                    if (acq_load(&g_dep[t - 1][mb]) >= NBK) s_ready = 1u;
                    else dep_wait2(&g_dep2[t - 1][mb][nc]);
                }
            }
            __syncthreads();
            load_chunk(smb, tid, c + NSTAGE, t, pp, mb, nb);
        }
        // drain remaining cp.async groups so next task's loads are clean
        asm volatile("cp.async.wait_group 0;" ::: "memory");

        // ---- fused LSTM cell epilogue (L1-bypass: cross-SM step handoff) ----
        const int o0 = nb * 32 + (wid & 3) * 8 + (lane & 3) * 2;
        const int chunk = nb >> 1;
        const int kk0 = o0 & 63;
        const int last = (t == TT - 1);
        float bi0 = bias[o0],            bi1 = bias[o0 + 1];
        float bf0 = bias[HDIM + o0],     bf1 = bias[HDIM + o0 + 1];
        float bg0 = bias[2*HDIM + o0],   bg1 = bias[2*HDIM + o0 + 1];
        float bo0 = bias[3*HDIM + o0],   bo1 = bias[3*HDIM + o0 + 1];
        char* th = (char*)&g_Ah[pp ^ 1][mb][chunk][0];

#pragma unroll
        for (int mi = 0; mi < 4; mi++) {
#pragma unroll
            for (int b2 = 0; b2 < 2; b2++) {
                int mrow = mw + mi * 16 + r4 + b2 * 8;
                int m = mb * 128 + mrow;
                size_t cidx = (size_t)m * HDIM + o0;
                float2 cold = __ldcg((const float2*)&g_c[cidx]);
                float gi0 = acc[mi][0][b2 * 2],     gi1 = acc[mi][0][b2 * 2 + 1];
                float gf0 = acc[mi][1][b2 * 2],     gf1 = acc[mi][1][b2 * 2 + 1];
                float gg0 = acc[mi][2][b2 * 2],     gg1 = acc[mi][2][b2 * 2 + 1];
                float go0 = acc[mi][3][b2 * 2],     go1 = acc[mi][3][b2 * 2 + 1];
                float cn0 = sigmoidf_(gf0 + bf0) * cold.x
                          + sigmoidf_(gi0 + bi0) * tanhf(gg0 + bg0);
                float cn1 = sigmoidf_(gf1 + bf1) * cold.y
                          + sigmoidf_(gi1 + bi1) * tanhf(gg1 + bg1);
                float h0 = sigmoidf_(go0 + bo0) * tanhf(cn0);
                float h1 = sigmoidf_(go1 + bo1) * tanhf(cn1);
                __stcg((float2*)&g_c[cidx], make_float2(cn0, cn1));
                if (last) *(float2*)&g_hf[cidx] = make_float2(h0, h1);
                uint32_t hv = hpack(h0, h1);
                asm volatile("st.global.cg.u32 [%0], %1;"
                             :: "l"(th + aoff(mrow, kk0)), "r"(hv) : "memory");
            }
        }

        // publish: fine counter first (release), then coarse
        __threadfence();
        __syncthreads();
        if (tid == 0) {
            atomicAdd(&g_dep2[t][mb][chunk], 1u);
            __threadfence();
            atomicAdd(&g_dep[t][mb], 1u);
        }
    }
}

// ---------------------------------------------------------------------------
// Persistent key pass: ONE grid barrier/step; each CTA keeps a private copy
// of its 64-col h/c slice; gates go to per-step buffers (no clearing).
// ---------------------------------------------------------------------------
__device__ __forceinline__ void grid_bar(unsigned int* phase)
{
    __syncthreads();
    if (threadIdx.x == 0) {
        __threadfence();
        atomicAdd(&g_kbar, 1u);
        unsigned int target = *phase + KGRID;
        for (;;) {
            if (acq_load(&g_kbar) >= target) break;
            __nanosleep(64);
        }
    }
    *phase += KGRID;
    __syncthreads();
}

__global__ void __launch_bounds__(256, 2)
key_persist(const float* __restrict__ key, const float* __restrict__ bias)
{
    __shared__ float hs[KBATCH][KC];
    __shared__ float cs[KBATCH][KC];
    const int bid = blockIdx.x;
    const int cb = bid & 15;      // col block 0..15
    const int ks = bid >> 4;      // chunk 0..16
    const int tid = threadIdx.x;

    const int col = cb * 256 + tid;
    const int gate = col >> 10, c10 = col & 1023;
    const int nbb = c10 >> 5, w2 = (c10 >> 3) & 3, ol = c10 & 7;
    const int n = w2 * 32 + gate * 8 + ol;
    const char* th = (const char*)&g_Wh[nbb][ks][0] + n * 128;
    const char* tl = (const char*)&g_Wl[nbb][ks][0] + n * 128;

    // private state init (h=0, c=0); for ks==16, hs is x staging (zero pad)
    for (int i = tid; i < KBATCH * KC; i += 256) {
        hs[i >> 6][i & 63] = 0.f;
        cs[i >> 6][i & 63] = 0.f;
    }
    __syncthreads();

    unsigned int phase = 0;

    for (int t = 0; t < TT; t++) {
        if (ks == 16) {
            for (int i = tid; i < KBATCH * KC; i += 256) {
                int mm = i >> 6, kk = i & 63;
                if (kk < DD) hs[mm][kk] = key[(size_t)(mm * TT + t) * DD + kk];
            }
            __syncthreads();
        }

        float acc[KBATCH];
#pragma unroll
        for (int mm = 0; mm < KBATCH; mm++) acc[mm] = 0.f;

#pragma unroll
        for (int g = 0; g < 8; g++) {
            uint32_t off = (uint32_t)(((g ^ n) & 7) << 4);
            uint4 vh = *(const uint4*)(th + off);
            uint4 vl = *(const uint4*)(tl + off);
            const __half2* ph = (const __half2*)&vh;
            const __half2* pl = (const __half2*)&vl;
#pragma unroll
            for (int j = 0; j < 4; j++) {
                float2 fh = __half22float2(ph[j]);
                float2 fl = __half22float2(pl[j]);
                float w0 = fh.x + fl.x, w1 = fh.y + fl.y;
                int k0 = g * 8 + j * 2;
#pragma unroll
                for (int mm = 0; mm < KBATCH; mm++)
                    acc[mm] += hs[mm][k0] * w0 + hs[mm][k0 + 1] * w1;
            }
        }
#pragma unroll
        for (int mm = 0; mm < KBATCH; mm++)
            atomicAdd(&g_gk3[t][mm][col], acc[mm]);

        grid_bar(&phase);   // all gate adds for step t complete

        if (ks < 16) {
            // cell update on this CTA's private slice (cols ks*64 .. +63)
            for (int i = tid; i < KBATCH * KC; i += 256) {
                int mm = i >> 6, kk = i & 63, nn = ks * KC + kk;
                float gi = __ldcg(&g_gk3[t][mm][nn]) + bias[nn];
                float gf = __ldcg(&g_gk3[t][mm][HDIM + nn]) + bias[HDIM + nn];
                float gg = __ldcg(&g_gk3[t][mm][2 * HDIM + nn]) + bias[2 * HDIM + nn];
                float go = __ldcg(&g_gk3[t][mm][3 * HDIM + nn]) + bias[3 * HDIM + nn];
                float cold = cs[mm][kk];
                float cn = sigmoidf_(gf) * cold + sigmoidf_(gi) * tanhf(gg);
                cs[mm][kk] = cn;
                float hv = sigmoidf_(go) * tanhf(cn);
                hs[mm][kk] = hv;
                if (t == TT - 1 && cb == 0) {
                    g_hk[0][mm * HDIM + nn] = hv;
                    g_ck[mm * HDIM + nn] = cn;
                }
            }
            __syncthreads();   // hs ready for next step's gemm
        }
    }
}

__global__ void key_init()
{
    size_t i0 = (size_t)blockIdx.x * blockDim.x + threadIdx.x;
    size_t total = (size_t)TT * KBATCH * GDIM;
    for (size_t i = i0; i < total; i += (size_t)gridDim.x * blockDim.x)
        ((float*)g_gk3)[i] = 0.f;
    if (i0 == 0) { g_ticket = 0u; g_kbar = 0u; }
    if (i0 < TT * MBK) g_dep[i0 / MBK][i0 % MBK] = 0u;
    if (i0 < (size_t)TT * MBK * 16) {
        unsigned int* d2 = &g_dep2[0][0][0];
        d2[i0] = 0u;
    }
}

__global__ void key_mean(int p)
{
    int n = blockIdx.x * blockDim.x + threadIdx.x;
    if (n < HDIM) {
        float sh = 0.f, sc = 0.f;
        for (int m = 0; m < KBATCH; m++) {
            sh += g_hk[p][m * HDIM + n];
            sc += g_ck[m * HDIM + n];
        }
        g_h0[n] = sh * (1.0f / KBATCH);
        g_c0[n] = sc * (1.0f / KBATCH);
    }
}

// broadcast h0/c0 into A tiles + c
__global__ void bcast_init()
{
    int mb = blockIdx.x, ch = blockIdx.y;
    int r = threadIdx.x;
    int m = mb * 128 + r;
    char* th = (char*)&g_Ah[0][mb][ch][0];
#pragma unroll
    for (int kk = 0; kk < KC; kk += 2) {
        int n = ch * KC + kk;
        float v0 = g_h0[n], v1 = g_h0[n + 1];
        *(uint32_t*)(th + aoff(r, kk)) = hpack(v0, v1);
        *(float2*)&g_c[(size_t)m * HDIM + n] = make_float2(g_c0[n], g_c0[n + 1]);
    }
}

// ---------------------------------------------------------------------------
__global__ void classify(const float* __restrict__ Wcls,
                         const float* __restrict__ bcls,
                         float* __restrict__ out)
{
    int gw = (blockIdx.x * blockDim.x + threadIdx.x) >> 5;
    int lane = threadIdx.x & 31;
    if (gw >= BB) return;
    const float* hr = &g_hf[(size_t)gw * HDIM];
    float acc[10];
#pragma unroll
    for (int c = 0; c < 10; c++) acc[c] = 0.f;
    for (int k = lane; k < HDIM; k += 32) {
        float hv = hr[k];
#pragma unroll
        for (int c = 0; c < 10; c++) acc[c] += hv * Wcls[k * 10 + c];
    }
#pragma unroll
    for (int c = 0; c < 10; c++) {
#pragma unroll
        for (int off = 16; off > 0; off >>= 1)
            acc[c] += __shfl_down_sync(0xffffffffu, acc[c], off);
    }
    if (lane == 0) {
#pragma unroll
        for (int c = 0; c < 10; c++)
            out[(size_t)gw * 10 + c] = acc[c] + bcls[c];
    }
}

// ---------------------------------------------------------------------------
extern "C" void kernel_launch(void* const* d_in, const int* in_sizes, int n_in,
                              void* d_out, int out_size)
{
    const float* x    = (const float*)d_in[0];
    const float* key  = (const float*)d_in[1];
    const float* Wih  = (const float*)d_in[2];
    const float* Whh  = (const float*)d_in[3];
    const float* b    = (const float*)d_in[4];
    const float* Wcls = (const float*)d_in[5];
    const float* bcls = (const float*)d_in[6];
    float* out = (float*)d_out;

    cudaFuncSetAttribute(data_persist, cudaFuncAttributeMaxDynamicSharedMemorySize,
                         SMEM_DATA);

    prep_W<<<dim3(CPT, NBK), 256>>>(Wih, Whh);
    prep_x<<<dim3(MBK, TT), 128>>>(x);

    key_init<<<256, 256>>>();
    key_persist<<<KGRID, 256>>>(key, b);
    key_mean<<<(HDIM + 255) / 256, 256>>>(0);
    bcast_init<<<dim3(MBK, 16), 128>>>();

    // Data pass: single persistent kernel, fine-grained cross-step deps
    data_persist<<<PGRID, 256, SMEM_DATA>>>(b);

    classify<<<BB / 8, 256>>>(Wcls, bcls, out);
}

// round 17
// speedup vs baseline: 1.1172x; 1.1172x over previous
#include <cuda_runtime.h>
#include <cuda_fp16.h>
#include <cstdint>
#include <math.h>

#define HDIM 1024
#define GDIM 4096
#define TT 28
#define DD 28
#define BB 4096
#define KBATCH 8

// GEMM: C[4096 x 4096gates], SINGLE fp16 term, per-K-chunk
// CTA tile 128m x 128n, warp tile 64x32, NSTAGE=3 x 32KB -> 96KB -> 2 CTA/SM
// Data pass: persistent kernel, ticket scheduler, coarse per-(t,mb) deps,
//            SINGLE-sync mainloop, fast-MUFU cell epilogue
// Key pass : persistent kernel, ONE grid barrier/step, private h/c slices
#define KC 64
#define CPT 17            // K-chunks (16 h-chunks + 1 x-chunk)
#define NSTAGE 3
#define TILE_BYTES 16384  // 128 x 64 fp16
#define STAGE_BYTES 32768 // Ah + Bh
#define SMEM_DATA (NSTAGE * STAGE_BYTES)   // 96 KB
#define MBK 32            // 4096/128 M-blocks
#define NBK 32            // 1024/32 out-blocks (128 gate-cols per CTA)
#define NTASK (TT * MBK * NBK)
#define PGRID 296         // 2 CTAs x 148 SMs, all resident
#define KGRID 272         // key pass: 16 col-blocks x 17 chunks, all resident

// ---------------- persistent scratch ----------------
__device__ __half g_Wh[NBK][CPT][8192];
__device__ __half g_Wl[NBK][CPT][8192];
__device__ __half g_Ah[2][MBK][16][8192];   // h tiles (fp16 rounded), ping-pong
__device__ __half g_xh[TT][MBK][8192];
__device__ float g_c[(size_t)BB * HDIM];
__device__ float g_hf[(size_t)BB * HDIM];
__device__ float g_hk[2][KBATCH * HDIM];
__device__ float g_ck[KBATCH * HDIM];
__device__ float g_gk3[TT][KBATCH][GDIM];   // per-step gate buffers (no clearing)
__device__ float g_h0[HDIM];
__device__ float g_c0[HDIM];
__device__ unsigned int g_ticket;
__device__ unsigned int g_dep[TT][MBK];     // coarse: 32 tiles per (t,mb)
__device__ unsigned int g_kbar;

// ---------------- helpers ----------------
// fast sigmoid/tanh: MUFU.EX2 + MUFU.RCP, rel err ~1e-6
__device__ __forceinline__ float sigf(float x) {
    return __fdividef(1.0f, 1.0f + __expf(-x));
}
__device__ __forceinline__ float tanhf_(float x) {
    return __fdividef(2.0f, 1.0f + __expf(-2.0f * x)) - 1.0f;
}

// swizzled byte offset within a [rows x 64] fp16 tile (128B rows, 16B groups)
__device__ __forceinline__ uint32_t aoff(int row, int kk) {
    return (uint32_t)(row * 128 + ((((kk >> 3) ^ row) & 7) << 4) + (kk & 7) * 2);
}

__device__ __forceinline__ uint32_t smem_u32(const void* p) {
    uint32_t a;
    asm("{ .reg .u64 t; cvta.to.shared.u64 t, %1; cvt.u32.u64 %0, t; }" : "=r"(a) : "l"(p));
    return a;
}

__device__ __forceinline__ uint32_t hpack(float v0, float v1) {
    __half2 p = __floats2half2_rn(v0, v1);
    return *(uint32_t*)&p;
}

__device__ __forceinline__ unsigned int acq_load(const unsigned int* p) {
    unsigned int v;
    asm volatile("ld.acquire.gpu.global.u32 %0, [%1];" : "=r"(v) : "l"(p));
    return v;
}

#define CP_ASYNC16(dst, src) \
    asm volatile("cp.async.cg.shared.global [%0], [%1], 16;" :: "r"(dst), "l"(src))
#define CP_COMMIT() asm volatile("cp.async.commit_group;" ::: "memory")
#define CP_WAIT1() asm volatile("cp.async.wait_group 1;" ::: "memory")

#define LDMX4(r0, r1, r2, r3, addr) \
    asm volatile("ldmatrix.sync.aligned.m8n8.x4.shared.b16 {%0,%1,%2,%3}, [%4];" \
        : "=r"(r0), "=r"(r1), "=r"(r2), "=r"(r3) : "r"(addr))
#define MMA16816(d, a, b0, b1) \
    asm volatile("mma.sync.aligned.m16n8k16.row.col.f32.f16.f16.f32 " \
        "{%0,%1,%2,%3},{%4,%5,%6,%7},{%8,%9},{%0,%1,%2,%3};" \
        : "+f"((d)[0]), "+f"((d)[1]), "+f"((d)[2]), "+f"((d)[3]) \
        : "r"((a)[0]), "r"((a)[1]), "r"((a)[2]), "r"((a)[3]), "r"(b0), "r"(b1))

// ---------------------------------------------------------------------------
// prep: fp16 hi/lo split of weights into swizzled [n][k] tiles.
// B tile row layout (128): warp w (n>>5), gate ((n>>3)&3), out_local (n&7)
// -> W column = gate*1024 + nb*32 + w*8 + ol ; tile row n = w*32+gate*8+ol
// ---------------------------------------------------------------------------
__global__ void prep_W(const float* __restrict__ Wih, const float* __restrict__ Whh)
{
    int kc = blockIdx.x, nb = blockIdx.y;
    int n = threadIdx.x & 127, kh = threadIdx.x >> 7;
    int w = n >> 5, gate = (n >> 3) & 3, ol = n & 7;
    int col = gate * HDIM + nb * 32 + w * 8 + ol;
    char* th = (char*)&g_Wh[nb][kc][0];
    char* tl = (char*)&g_Wl[nb][kc][0];
#pragma unroll
    for (int kk = kh * 32; kk < kh * 32 + 32; kk += 2) {
        float v0, v1;
        if (kc < 16) {
            size_t kg = (size_t)(kc * 64 + kk);
            v0 = Whh[kg * GDIM + col];
            v1 = Whh[(kg + 1) * GDIM + col];
        } else {
            v0 = (kk < DD) ? Wih[(size_t)kk * GDIM + col] : 0.f;
            v1 = (kk + 1 < DD) ? Wih[(size_t)(kk + 1) * GDIM + col] : 0.f;
        }
        float h0 = __half2float(__float2half_rn(v0));
        float h1 = __half2float(__float2half_rn(v1));
        uint32_t off = aoff(n, kk);
        *(uint32_t*)(th + off) = hpack(h0, h1);
        *(uint32_t*)(tl + off) = hpack(v0 - h0, v1 - h1);
    }
}

__global__ void prep_x(const float* __restrict__ x)
{
    int mb = blockIdx.x, t = blockIdx.y;
    int r = threadIdx.x;
    int m = mb * 128 + r;
    char* th = (char*)&g_xh[t][mb][0];
#pragma unroll
    for (int kk = 0; kk < KC; kk += 2) {
        float v0 = (kk < DD) ? x[((size_t)m * TT + t) * DD + kk] : 0.f;
        float v1 = (kk + 1 < DD) ? x[((size_t)m * TT + t) * DD + kk + 1] : 0.f;
        *(uint32_t*)(th + aoff(r, kk)) = hpack(v0, v1);
    }
}

// ---------------------------------------------------------------------------
// Persistent data pass: ticket scheduler + coarse deps + single-sync mainloop
// Stage layout: [Ah 16K][Bh 16K]
// ---------------------------------------------------------------------------
__device__ __forceinline__ void load_chunk(uint32_t smb, int tid, int c,
                                           int t, int pp, int mb, int nb)
{
    if (c < CPT) {
        const char* ah = (c == 16) ? (const char*)&g_xh[t][mb][0]
                                   : (const char*)&g_Ah[pp][mb][c][0];
        const char* bh = (const char*)&g_Wh[nb][c][0];
        uint32_t dst = smb + (c % NSTAGE) * STAGE_BYTES;
        int o = tid * 16;
#pragma unroll
        for (int i = 0; i < 4; i++) {
            CP_ASYNC16(dst + o,              ah + o);
            CP_ASYNC16(dst + TILE_BYTES + o, bh + o);
            o += 4096;
        }
    }
    CP_COMMIT();
}

__global__ void __launch_bounds__(256, 2)
data_persist(const float* __restrict__ bias)
{
    extern __shared__ __align__(128) char sm[];
    const uint32_t smb = smem_u32(sm);
    __shared__ unsigned int s_task;
    const int tid = threadIdx.x, wid = tid >> 5, lane = tid & 31;
    const int mw = (wid >> 2) * 64;       // warp m offset
    const int nw = (wid & 3) * 32;        // warp n(col) offset

    // lane geometry (task-invariant)
    const int a_row0 = mw + ((lane >> 3) & 1) * 8 + (lane & 7);   // + mi*16
    const int a_ghalf = lane >> 4;
    const int b_row0 = nw + ((lane >> 4) & 1) * 8 + (lane & 7);   // + 16 for ni 2,3
    const int b_ghalf = (lane >> 3) & 1;
    const int r4 = lane >> 2;

    for (;;) {
        if (tid == 0) s_task = atomicAdd(&g_ticket, 1u);
        __syncthreads();
        const unsigned int task = s_task;
        if (task >= NTASK) return;
        const int t  = task >> 10;
        const int mb = (task >> 5) & 31;
        const int nb = task & 31;
        const int pp = t & 1;

        // wait for step t-1 of this mb chain (coarse)
        if (t > 0 && tid == 0) {
            const unsigned int* dp = &g_dep[t - 1][mb];
            for (;;) {
                if (acq_load(dp) >= NBK) break;
                __nanosleep(128);
            }
        }
        __syncthreads();

        float acc[4][4][4];
#pragma unroll
        for (int i = 0; i < 4; i++)
#pragma unroll
            for (int j = 0; j < 4; j++)
#pragma unroll
                for (int q = 0; q < 4; q++) acc[i][j][q] = 0.f;

        load_chunk(smb, tid, 0, t, pp, mb, nb);
        load_chunk(smb, tid, 1, t, pp, mb, nb);

        for (int c = 0; c < CPT; c++) {
            CP_WAIT1();
            __syncthreads();
            // prefetch c+2 into the slot chunk c-1 occupied (just proven consumed)
            load_chunk(smb, tid, c + 2, t, pp, mb, nb);

            uint32_t sAh = smb + (c % NSTAGE) * STAGE_BYTES;
            uint32_t sBh = sAh + TILE_BYTES;
#pragma unroll
            for (int kb = 0; kb < 4; kb++) {
                const uint32_t acsw = (uint32_t)((((2 * kb + a_ghalf) ^ a_row0) & 7) << 4);
                const uint32_t bcsw = (uint32_t)((((2 * kb + b_ghalf) ^ b_row0) & 7) << 4);
                const uint32_t brow = (uint32_t)b_row0 * 128 + bcsw;

                uint32_t ah[4][4], bh[8];
#pragma unroll
                for (int mi = 0; mi < 4; mi++) {
                    uint32_t ad = sAh + (uint32_t)(a_row0 + mi * 16) * 128 + acsw;
                    LDMX4(ah[mi][0], ah[mi][1], ah[mi][2], ah[mi][3], ad);
                }
                LDMX4(bh[0], bh[1], bh[2], bh[3], sBh + brow);
                LDMX4(bh[4], bh[5], bh[6], bh[7], sBh + brow + 2048);
#pragma unroll
                for (int ni = 0; ni < 4; ni++)
#pragma unroll
                    for (int mi = 0; mi < 4; mi++)
                        MMA16816(acc[mi][ni], ah[mi], bh[ni * 2], bh[ni * 2 + 1]);
            }
        }
        // drain remaining cp.async groups so next task's loads are clean
        asm volatile("cp.async.wait_group 0;" ::: "memory");

        // ---- fused LSTM cell epilogue (fast MUFU math, L1-bypass handoff) ----
        const int o0 = nb * 32 + (wid & 3) * 8 + (lane & 3) * 2;
        const int chunk = nb >> 1;
        const int kk0 = o0 & 63;
        const int last = (t == TT - 1);
        float bi0 = bias[o0],            bi1 = bias[o0 + 1];
        float bf0 = bias[HDIM + o0],     bf1 = bias[HDIM + o0 + 1];
        float bg0 = bias[2*HDIM + o0],   bg1 = bias[2*HDIM + o0 + 1];
        float bo0 = bias[3*HDIM + o0],   bo1 = bias[3*HDIM + o0 + 1];
        char* th = (char*)&g_Ah[pp ^ 1][mb][chunk][0];

#pragma unroll
        for (int mi = 0; mi < 4; mi++) {
#pragma unroll
            for (int b2 = 0; b2 < 2; b2++) {
                int mrow = mw + mi * 16 + r4 + b2 * 8;
                int m = mb * 128 + mrow;
                size_t cidx = (size_t)m * HDIM + o0;
                float2 cold = __ldcg((const float2*)&g_c[cidx]);
                float gi0 = acc[mi][0][b2 * 2],     gi1 = acc[mi][0][b2 * 2 + 1];
                float gf0 = acc[mi][1][b2 * 2],     gf1 = acc[mi][1][b2 * 2 + 1];
                float gg0 = acc[mi][2][b2 * 2],     gg1 = acc[mi][2][b2 * 2 + 1];
                float go0 = acc[mi][3][b2 * 2],     go1 = acc[mi][3][b2 * 2 + 1];
                float cn0 = sigf(gf0 + bf0) * cold.x
                          + sigf(gi0 + bi0) * tanhf_(gg0 + bg0);
                float cn1 = sigf(gf1 + bf1) * cold.y
                          + sigf(gi1 + bi1) * tanhf_(gg1 + bg1);
                float h0 = sigf(go0 + bo0) * tanhf_(cn0);
                float h1 = sigf(go1 + bo1) * tanhf_(cn1);
                __stcg((float2*)&g_c[cidx], make_float2(cn0, cn1));
                if (last) *(float2*)&g_hf[cidx] = make_float2(h0, h1);
                uint32_t hv = hpack(h0, h1);
                asm volatile("st.global.cg.u32 [%0], %1;"
                             :: "l"(th + aoff(mrow, kk0)), "r"(hv) : "memory");
            }
        }

        // publish completion
        __threadfence();
        __syncthreads();
        if (tid == 0) atomicAdd(&g_dep[t][mb], 1u);
    }
}

// ---------------------------------------------------------------------------
// Persistent key pass: ONE grid barrier/step; private h/c slices per CTA;
// per-step gate buffers (no clearing).
// ---------------------------------------------------------------------------
__device__ __forceinline__ void grid_bar(unsigned int* phase)
{
    __syncthreads();
    if (threadIdx.x == 0) {
        __threadfence();
        atomicAdd(&g_kbar, 1u);
        unsigned int target = *phase + KGRID;
        for (;;) {
            if (acq_load(&g_kbar) >= target) break;
            __nanosleep(64);
        }
    }
    *phase += KGRID;
    __syncthreads();
}

__global__ void __launch_bounds__(256, 2)
key_persist(const float* __restrict__ key, const float* __restrict__ bias)
{
    __shared__ float hs[KBATCH][KC];
    __shared__ float cs[KBATCH][KC];
    const int bid = blockIdx.x;
    const int cb = bid & 15;      // col block 0..15
    const int ks = bid >> 4;      // chunk 0..16
    const int tid = threadIdx.x;

    const int col = cb * 256 + tid;
    const int gate = col >> 10, c10 = col & 1023;
    const int nbb = c10 >> 5, w2 = (c10 >> 3) & 3, ol = c10 & 7;
    const int n = w2 * 32 + gate * 8 + ol;
    const char* th = (const char*)&g_Wh[nbb][ks][0] + n * 128;
    const char* tl = (const char*)&g_Wl[nbb][ks][0] + n * 128;

    for (int i = tid; i < KBATCH * KC; i += 256) {
        hs[i >> 6][i & 63] = 0.f;
        cs[i >> 6][i & 63] = 0.f;
    }
    __syncthreads();

    unsigned int phase = 0;

    for (int t = 0; t < TT; t++) {
        if (ks == 16) {
            for (int i = tid; i < KBATCH * KC; i += 256) {
                int mm = i >> 6, kk = i & 63;
                if (kk < DD) hs[mm][kk] = key[(size_t)(mm * TT + t) * DD + kk];
            }
            __syncthreads();
        }

        float acc[KBATCH];
#pragma unroll
        for (int mm = 0; mm < KBATCH; mm++) acc[mm] = 0.f;

#pragma unroll
        for (int g = 0; g < 8; g++) {
            uint32_t off = (uint32_t)(((g ^ n) & 7) << 4);
            uint4 vh = *(const uint4*)(th + off);
            uint4 vl = *(const uint4*)(tl + off);
            const __half2* ph = (const __half2*)&vh;
            const __half2* pl = (const __half2*)&vl;
#pragma unroll
            for (int j = 0; j < 4; j++) {
                float2 fh = __half22float2(ph[j]);
                float2 fl = __half22float2(pl[j]);
                float w0 = fh.x + fl.x, w1 = fh.y + fl.y;
                int k0 = g * 8 + j * 2;
#pragma unroll
                for (int mm = 0; mm < KBATCH; mm++)
                    acc[mm] += hs[mm][k0] * w0 + hs[mm][k0 + 1] * w1;
            }
        }
#pragma unroll
        for (int mm = 0; mm < KBATCH; mm++)
            atomicAdd(&g_gk3[t][mm][col], acc[mm]);

        grid_bar(&phase);   // all gate adds for step t complete

        if (ks < 16) {
            for (int i = tid; i < KBATCH * KC; i += 256) {
                int mm = i >> 6, kk = i & 63, nn = ks * KC + kk;
                float gi = __ldcg(&g_gk3[t][mm][nn]) + bias[nn];
                float gf = __ldcg(&g_gk3[t][mm][HDIM + nn]) + bias[HDIM + nn];
                float gg = __ldcg(&g_gk3[t][mm][2 * HDIM + nn]) + bias[2 * HDIM + nn];
                float go = __ldcg(&g_gk3[t][mm][3 * HDIM + nn]) + bias[3 * HDIM + nn];
                float cold = cs[mm][kk];
                float cn = sigf(gf) * cold + sigf(gi) * tanhf_(gg);
                cs[mm][kk] = cn;
                float hv = sigf(go) * tanhf_(cn);
                hs[mm][kk] = hv;
                if (t == TT - 1 && cb == 0) {
                    g_hk[0][mm * HDIM + nn] = hv;
                    g_ck[mm * HDIM + nn] = cn;
                }
            }
            __syncthreads();   // hs ready for next step's gemm
        }
    }
}

__global__ void key_init()
{
    size_t i0 = (size_t)blockIdx.x * blockDim.x + threadIdx.x;
    size_t total = (size_t)TT * KBATCH * GDIM;
    for (size_t i = i0; i < total; i += (size_t)gridDim.x * blockDim.x)
        ((float*)g_gk3)[i] = 0.f;
    if (i0 == 0) { g_ticket = 0u; g_kbar = 0u; }
    if (i0 < TT * MBK) g_dep[i0 / MBK][i0 % MBK] = 0u;
}

__global__ void key_mean(int p)
{
    int n = blockIdx.x * blockDim.x + threadIdx.x;
    if (n < HDIM) {
        float sh = 0.f, sc = 0.f;
        for (int m = 0; m < KBATCH; m++) {
            sh += g_hk[p][m * HDIM + n];
            sc += g_ck[m * HDIM + n];
        }
        g_h0[n] = sh * (1.0f / KBATCH);
        g_c0[n] = sc * (1.0f / KBATCH);
    }
}

// broadcast h0/c0 into A tiles + c
__global__ void bcast_init()
{
    int mb = blockIdx.x, ch = blockIdx.y;
    int r = threadIdx.x;
    int m = mb * 128 + r;
    char* th = (char*)&g_Ah[0][mb][ch][0];
#pragma unroll
    for (int kk = 0; kk < KC; kk += 2) {
        int n = ch * KC + kk;
        float v0 = g_h0[n], v1 = g_h0[n + 1];
        *(uint32_t*)(th + aoff(r, kk)) = hpack(v0, v1);
        *(float2*)&g_c[(size_t)m * HDIM + n] = make_float2(g_c0[n], g_c0[n + 1]);
    }
}

// ---------------------------------------------------------------------------
__global__ void classify(const float* __restrict__ Wcls,
                         const float* __restrict__ bcls,
                         float* __restrict__ out)
{
    int gw = (blockIdx.x * blockDim.x + threadIdx.x) >> 5;
    int lane = threadIdx.x & 31;
    if (gw >= BB) return;
    const float* hr = &g_hf[(size_t)gw * HDIM];
    float acc[10];
#pragma unroll
    for (int c = 0; c < 10; c++) acc[c] = 0.f;
    for (int k = lane; k < HDIM; k += 32) {
        float hv = hr[k];
#pragma unroll
        for (int c = 0; c < 10; c++) acc[c] += hv * Wcls[k * 10 + c];
    }
#pragma unroll
    for (int c = 0; c < 10; c++) {
#pragma unroll
        for (int off = 16; off > 0; off >>= 1)
            acc[c] += __shfl_down_sync(0xffffffffu, acc[c], off);
    }
    if (lane == 0) {
#pragma unroll
        for (int c = 0; c < 10; c++)
            out[(size_t)gw * 10 + c] = acc[c] + bcls[c];
    }
}

// ---------------------------------------------------------------------------
extern "C" void kernel_launch(void* const* d_in, const int* in_sizes, int n_in,
                              void* d_out, int out_size)
{
    const float* x    = (const float*)d_in[0];
    const float* key  = (const float*)d_in[1];
    const float* Wih  = (const float*)d_in[2];
    const float* Whh  = (const float*)d_in[3];
    const float* b    = (const float*)d_in[4];
    const float* Wcls = (const float*)d_in[5];
    const float* bcls = (const float*)d_in[6];
    float* out = (float*)d_out;

    cudaFuncSetAttribute(data_persist, cudaFuncAttributeMaxDynamicSharedMemorySize,
                         SMEM_DATA);

    prep_W<<<dim3(CPT, NBK), 256>>>(Wih, Whh);
    prep_x<<<dim3(MBK, TT), 128>>>(x);

    key_init<<<256, 256>>>();
    key_persist<<<KGRID, 256>>>(key, b);
    key_mean<<<(HDIM + 255) / 256, 256>>>(0);
    bcast_init<<<dim3(MBK, 16), 128>>>();

    // Data pass: single persistent kernel, coarse deps, single-sync mainloop
    data_persist<<<PGRID, 256, SMEM_DATA>>>(b);

    classify<<<BB / 8, 256>>>(Wcls, bcls, out);
}